// round 2
// baseline (speedup 1.0000x reference)
#include <cuda_runtime.h>
#include <math_constants.h>

// Problem constants (fixed shapes from reference):
//   x: (4,2048,1024) -> 8192 x 1024
//   patterns: 4096 x 1024
//   Wq, Wk: 1024 x 1024
//   N_STEPS = 3, BETA = 1.0
#define ROWS_Q 8192
#define DIM_C  1024
#define DIM_M  4096

#define BM 128
#define BN 128
#define BK 32
#define PAD 132   // 132*4B = 528B rows: keeps float4 alignment, spreads banks

// Scratch (no allocations allowed -> __device__ globals)
__device__ float g_state[(size_t)ROWS_Q * DIM_C];   // 32 MB
__device__ float g_k[(size_t)DIM_M * DIM_C];        // 16 MB
__device__ float g_sim[(size_t)ROWS_Q * DIM_M];     // 128 MB

// ----------------------------------------------------------------------------
// Tiled fp32 GEMM.
//  TRANS_B = true : C[i][j] = sum_k A[i][k] * B[j][k]   (B stored N x K)
//  TRANS_B = false: C[i][j] = sum_k A[i][k] * B[k][j]   (B stored K x N)
//  MODE 0: C = A*B
//  MODE 1: C = 0.5*Cprev + 0.5*A*B   (state update)
// M, N, K must be multiples of 128/128/32 (true for all calls here).
// ----------------------------------------------------------------------------
template <bool TRANS_B, int MODE>
__global__ __launch_bounds__(256, 2)
void gemm_kernel(const float* __restrict__ A, const float* __restrict__ B,
                 float* __restrict__ C, const float* __restrict__ Cprev,
                 int M, int N, int K)
{
    __shared__ float As[BK][PAD];
    __shared__ float Bs[BK][PAD];

    const int tid = threadIdx.x;
    const int bm = blockIdx.y * BM;
    const int bn = blockIdx.x * BN;
    const int tx = tid & 15;        // 0..15 -> column group
    const int ty = tid >> 4;        // 0..15 -> row group

    float acc[64];
#pragma unroll
    for (int i = 0; i < 64; i++) acc[i] = 0.0f;

    // K-major loaders (A always; B when TRANS_B): float4 along K, transpose into smem
    const int lk4 = (tid & 7) * 4;  // 0,4,...,28
    const int lm  = tid >> 3;       // 0..31
    // N-major loader (B when !TRANS_B): float4 along N
    const int nn4 = (tid & 31) * 4; // 0..124
    const int nk  = tid >> 5;       // 0..7

    for (int k0 = 0; k0 < K; k0 += BK) {
        // ---- load A tile (128 x 32), store transposed As[k][m]
#pragma unroll
        for (int p = 0; p < 4; p++) {
            const int m = lm + 32 * p;
            float4 v = *(const float4*)&A[(size_t)(bm + m) * K + k0 + lk4];
            As[lk4 + 0][m] = v.x;
            As[lk4 + 1][m] = v.y;
            As[lk4 + 2][m] = v.z;
            As[lk4 + 3][m] = v.w;
        }
        // ---- load B tile
        if (TRANS_B) {
#pragma unroll
            for (int p = 0; p < 4; p++) {
                const int n = lm + 32 * p;
                float4 v = *(const float4*)&B[(size_t)(bn + n) * K + k0 + lk4];
                Bs[lk4 + 0][n] = v.x;
                Bs[lk4 + 1][n] = v.y;
                Bs[lk4 + 2][n] = v.z;
                Bs[lk4 + 3][n] = v.w;
            }
        } else {
#pragma unroll
            for (int p = 0; p < 4; p++) {
                const int kk = nk + 8 * p;
                float4 v = *(const float4*)&B[(size_t)(k0 + kk) * N + bn + nn4];
                *(float4*)&Bs[kk][nn4] = v;
            }
        }
        __syncthreads();

#pragma unroll
        for (int k = 0; k < BK; k++) {
            float a[8], b[8];
            float4 a0 = *(const float4*)&As[k][ty * 4];
            float4 a1 = *(const float4*)&As[k][ty * 4 + 64];
            float4 b0 = *(const float4*)&Bs[k][tx * 4];
            float4 b1 = *(const float4*)&Bs[k][tx * 4 + 64];
            a[0]=a0.x; a[1]=a0.y; a[2]=a0.z; a[3]=a0.w;
            a[4]=a1.x; a[5]=a1.y; a[6]=a1.z; a[7]=a1.w;
            b[0]=b0.x; b[1]=b0.y; b[2]=b0.z; b[3]=b0.w;
            b[4]=b1.x; b[5]=b1.y; b[6]=b1.z; b[7]=b1.w;
#pragma unroll
            for (int i = 0; i < 8; i++)
#pragma unroll
                for (int j = 0; j < 8; j++)
                    acc[i * 8 + j] = fmaf(a[i], b[j], acc[i * 8 + j]);
        }
        __syncthreads();
    }

    // ---- epilogue: 2x2 blocks of 4x4, float4 stores
#pragma unroll
    for (int ii = 0; ii < 2; ii++) {
#pragma unroll
        for (int r = 0; r < 4; r++) {
            const int row = bm + ty * 4 + ii * 64 + r;
            const int ai = ii * 4 + r;
#pragma unroll
            for (int jj = 0; jj < 2; jj++) {
                const int col = bn + tx * 4 + jj * 64;
                float4 v;
                v.x = acc[ai * 8 + jj * 4 + 0];
                v.y = acc[ai * 8 + jj * 4 + 1];
                v.z = acc[ai * 8 + jj * 4 + 2];
                v.w = acc[ai * 8 + jj * 4 + 3];
                if (MODE == 1) {
                    float4 pv = *(const float4*)&Cprev[(size_t)row * N + col];
                    v.x = 0.5f * v.x + 0.5f * pv.x;
                    v.y = 0.5f * v.y + 0.5f * pv.y;
                    v.z = 0.5f * v.z + 0.5f * pv.z;
                    v.w = 0.5f * v.w + 0.5f * pv.w;
                }
                *(float4*)&C[(size_t)row * N + col] = v;
            }
        }
    }
}

// ----------------------------------------------------------------------------
// Row softmax over 4096 columns, one block (256 threads) per row, in place.
// ----------------------------------------------------------------------------
__global__ __launch_bounds__(256)
void softmax_kernel(float* __restrict__ S)
{
    const int ncols = DIM_M;
    __shared__ float red[8];
    float* p = S + (size_t)blockIdx.x * ncols;
    const int tid = threadIdx.x;
    const int lane = tid & 31, warp = tid >> 5;

    // pass 1: max
    float m = -CUDART_INF_F;
    for (int c = tid * 4; c < ncols; c += 256 * 4) {
        float4 v = *(const float4*)&p[c];
        m = fmaxf(m, fmaxf(fmaxf(v.x, v.y), fmaxf(v.z, v.w)));
    }
#pragma unroll
    for (int o = 16; o > 0; o >>= 1) m = fmaxf(m, __shfl_xor_sync(0xffffffffu, m, o));
    if (lane == 0) red[warp] = m;
    __syncthreads();
    m = red[0];
#pragma unroll
    for (int w = 1; w < 8; w++) m = fmaxf(m, red[w]);
    __syncthreads();

    // pass 2: exp + sum (store exp back)
    const float LOG2E = 1.4426950408889634f;
    float s = 0.0f;
    for (int c = tid * 4; c < ncols; c += 256 * 4) {
        float4 v = *(const float4*)&p[c];
        v.x = exp2f((v.x - m) * LOG2E);
        v.y = exp2f((v.y - m) * LOG2E);
        v.z = exp2f((v.z - m) * LOG2E);
        v.w = exp2f((v.w - m) * LOG2E);
        s += (v.x + v.y) + (v.z + v.w);
        *(float4*)&p[c] = v;
    }
#pragma unroll
    for (int o = 16; o > 0; o >>= 1) s += __shfl_xor_sync(0xffffffffu, s, o);
    if (lane == 0) red[warp] = s;
    __syncthreads();
    s = red[0];
#pragma unroll
    for (int w = 1; w < 8; w++) s += red[w];
    const float rinv = 1.0f / s;

    // pass 3: scale
    for (int c = tid * 4; c < ncols; c += 256 * 4) {
        float4 v = *(const float4*)&p[c];
        v.x *= rinv; v.y *= rinv; v.z *= rinv; v.w *= rinv;
        *(float4*)&p[c] = v;
    }
}

// ----------------------------------------------------------------------------
extern "C" void kernel_launch(void* const* d_in, const int* in_sizes, int n_in,
                              void* d_out, int out_size)
{
    (void)in_sizes; (void)n_in; (void)out_size;
    const float* x        = (const float*)d_in[0];   // 8192 x 1024
    const float* patterns = (const float*)d_in[1];   // 4096 x 1024
    const float* Wq       = (const float*)d_in[2];   // 1024 x 1024
    const float* Wk       = (const float*)d_in[3];   // 1024 x 1024
    float* out = (float*)d_out;                      // 8192 x 1024

    float *state, *kmat, *sim;
    cudaGetSymbolAddress((void**)&state, g_state);
    cudaGetSymbolAddress((void**)&kmat,  g_k);
    cudaGetSymbolAddress((void**)&sim,   g_sim);

    dim3 block(256);

    // q = x @ Wq^T  -> state   (M=8192, N=1024, K=1024, B is NxK)
    gemm_kernel<true, 0><<<dim3(DIM_C / BN, ROWS_Q / BM), block>>>(
        x, Wq, state, nullptr, ROWS_Q, DIM_C, DIM_C);

    // k = patterns @ Wk^T  (M=4096, N=1024, K=1024)
    gemm_kernel<true, 0><<<dim3(DIM_C / BN, DIM_M / BM), block>>>(
        patterns, Wk, kmat, nullptr, DIM_M, DIM_C, DIM_C);

    for (int it = 0; it < 4; it++) {
        // sim = state @ k^T  (M=8192, N=4096, K=1024; BETA=1)
        gemm_kernel<true, 0><<<dim3(DIM_M / BN, ROWS_Q / BM), block>>>(
            state, kmat, sim, nullptr, ROWS_Q, DIM_M, DIM_C);

        // softmax rows
        softmax_kernel<<<ROWS_Q, block>>>(sim);

        if (it < 3) {
            // state = 0.5*state + 0.5*(attn @ patterns)  (M=8192, N=1024, K=4096)
            gemm_kernel<false, 1><<<dim3(DIM_C / BN, ROWS_Q / BM), block>>>(
                sim, patterns, state, state, ROWS_Q, DIM_C, DIM_M);
        } else {
            // output = attn @ patterns
            gemm_kernel<false, 0><<<dim3(DIM_C / BN, ROWS_Q / BM), block>>>(
                sim, patterns, out, nullptr, ROWS_Q, DIM_C, DIM_M);
        }
    }
}

// round 5
// speedup vs baseline: 2.4994x; 2.4994x over previous
#include <cuda_runtime.h>
#include <math_constants.h>
#include <cstdint>

// Shapes (fixed): x 8192x1024, patterns 4096x1024, Wq/Wk 1024x1024
#define ROWS_Q 8192
#define DIM_C  1024
#define DIM_M  4096

// Scratch (__device__ globals; no allocations allowed)
__device__ float g_state[(size_t)ROWS_Q * DIM_C];   // 32 MB
__device__ float g_k[(size_t)DIM_M * DIM_C];        // 16 MB
__device__ float g_sim[(size_t)ROWS_Q * DIM_M];     // 128 MB
__device__ float g_patT[(size_t)DIM_C * DIM_M];     // 16 MB

// ---------------------------------------------------------------------------
// cp.async helpers (sm_80+, valid for compute_103 PTX target)
// ---------------------------------------------------------------------------
__device__ __forceinline__ uint32_t smem_u32(const void* p) {
    uint32_t a;
    asm("{ .reg .u64 t; cvta.to.shared.u64 t, %1; cvt.u32.u64 %0, t; }"
        : "=r"(a) : "l"(p));
    return a;
}
__device__ __forceinline__ void cpa16(uint32_t dst, const void* src) {
    asm volatile("cp.async.cg.shared.global [%0], [%1], 16;\n" :: "r"(dst), "l"(src));
}
__device__ __forceinline__ void cp_commit() {
    asm volatile("cp.async.commit_group;\n" ::: "memory");
}
template <int N>
__device__ __forceinline__ void cp_wait() {
    asm volatile("cp.async.wait_group %0;\n" :: "n"(N) : "memory");
}

__device__ __forceinline__ uint32_t f2tf32(float f) {
    uint32_t r;
    asm("cvt.rna.tf32.f32 %0, %1;\n" : "=r"(r) : "f"(f));
    return r;
}

// mma.sync m16n8k8 tf32: D(16x8,f32) += A(16x8,tf32) * B(8x8,tf32)
__device__ __forceinline__ void mma_tf32(float* d, const uint32_t* a, const uint32_t* b) {
    asm volatile(
        "mma.sync.aligned.m16n8k8.row.col.f32.tf32.tf32.f32 "
        "{%0,%1,%2,%3}, {%4,%5,%6,%7}, {%8,%9}, {%0,%1,%2,%3};\n"
        : "+f"(d[0]), "+f"(d[1]), "+f"(d[2]), "+f"(d[3])
        : "r"(a[0]), "r"(a[1]), "r"(a[2]), "r"(a[3]), "r"(b[0]), "r"(b[1]));
}

// ---------------------------------------------------------------------------
// tf32 tensor-core GEMM: C[m][n] = sum_k A[m][k] * B[n][k]
//   A: M x K (row-major), B: N x K (row-major), C: M x ldC
//   Block tile 128x128x32, 256 threads (8 warps: 4 along M x 2 along N).
//   Warp tile 32x64 = 2 (M) x 8 (N) mma tiles of 16x8.
//   MODE 0: C = D ; MODE 1: C = 0.5*Cprev + 0.5*D
//   smem rows padded to 36 floats (144B): conflict-free fills and frag loads.
// ---------------------------------------------------------------------------
#define BM 128
#define BN 128
#define BK 32
#define ROWF 36                              // floats per smem row (144 B)
#define STAGE_FLOATS (2 * 128 * ROWF)        // A tile + B tile = 9216 floats
#define STAGES 4
#define GEMM_SMEM (STAGES * STAGE_FLOATS * 4)   // 147456 B

template <int MODE>
__global__ __launch_bounds__(256)
void tc_gemm(const float* __restrict__ A, const float* __restrict__ B,
             float* __restrict__ C, const float* __restrict__ Cprev,
             int K, int ldC)
{
    extern __shared__ float smem[];
    const int tid = threadIdx.x;
    const int wid = tid >> 5;
    const int lane = tid & 31;
    const int gid = lane >> 2;        // group id 0..7
    const int tig = lane & 3;         // thread-in-group 0..3
    const int warp_m = wid & 3;       // 0..3 -> 32-row band
    const int warp_n = wid >> 2;      // 0..1 -> 64-col band
    const int bm = blockIdx.y * BM;
    const int bn = blockIdx.x * BN;

    const uint32_t smem_b = smem_u32(smem);

    // ---- cooperative tile fill: 2048 x 16B chunks / 256 threads = 8 each
    auto load_tile = [&](int t, int s) {
        const uint32_t sb = smem_b + (uint32_t)s * (STAGE_FLOATS * 4);
        const int k0 = t * BK;
        const int r = tid >> 3;        // 0..31 base row
        const int j = tid & 7;         // chunk in row
#pragma unroll
        for (int p = 0; p < 4; p++) {  // A rows r, r+32, r+64, r+96
            const int row = r + 32 * p;
            cpa16(sb + row * 144 + j * 16, A + (size_t)(bm + row) * K + k0 + j * 4);
        }
#pragma unroll
        for (int p = 0; p < 4; p++) {  // B rows
            const int row = r + 32 * p;
            cpa16(sb + (128 + row) * 144 + j * 16, B + (size_t)(bn + row) * K + k0 + j * 4);
        }
        cp_commit();
    };

    float d[2][8][4];
#pragma unroll
    for (int mt = 0; mt < 2; mt++)
#pragma unroll
        for (int nt = 0; nt < 8; nt++)
#pragma unroll
            for (int i = 0; i < 4; i++) d[mt][nt][i] = 0.0f;

    const int T = K / BK;

    // prologue: 3 tiles in flight
    load_tile(0, 0);
    load_tile(1, 1);
    load_tile(2, 2);

    for (int t = 0; t < T; t++) {
        const int w = T - 1 - t;
        if (w >= 2) cp_wait<2>();
        else if (w == 1) cp_wait<1>();
        else cp_wait<0>();
        __syncthreads();

        const int nt_load = t + 3;
        if (nt_load < T) load_tile(nt_load, nt_load & (STAGES - 1));

        const float* As = smem + (t & (STAGES - 1)) * STAGE_FLOATS;
        const float* Bs = As + 128 * ROWF;

#pragma unroll
        for (int ks = 0; ks < 4; ks++) {
            const int k0 = ks * 8;
            uint32_t a[2][4], b[8][2];
#pragma unroll
            for (int mt = 0; mt < 2; mt++) {
                const int m0 = warp_m * 32 + mt * 16;
                a[mt][0] = f2tf32(As[(m0 + gid)     * ROWF + k0 + tig]);
                a[mt][1] = f2tf32(As[(m0 + gid + 8) * ROWF + k0 + tig]);
                a[mt][2] = f2tf32(As[(m0 + gid)     * ROWF + k0 + tig + 4]);
                a[mt][3] = f2tf32(As[(m0 + gid + 8) * ROWF + k0 + tig + 4]);
            }
#pragma unroll
            for (int nt = 0; nt < 8; nt++) {
                const int n0 = warp_n * 64 + nt * 8;
                b[nt][0] = f2tf32(Bs[(n0 + gid) * ROWF + k0 + tig]);
                b[nt][1] = f2tf32(Bs[(n0 + gid) * ROWF + k0 + tig + 4]);
            }
#pragma unroll
            for (int mt = 0; mt < 2; mt++)
#pragma unroll
                for (int nt = 0; nt < 8; nt++)
                    mma_tf32(d[mt][nt], a[mt], b[nt]);
        }
        __syncthreads();
    }

    // ---- epilogue: d regs -> C (float2 per fragment half-row)
#pragma unroll
    for (int mt = 0; mt < 2; mt++) {
        const int m0 = bm + warp_m * 32 + mt * 16 + gid;
#pragma unroll
        for (int half = 0; half < 2; half++) {
            const int row = m0 + half * 8;
            float* crow = C + (size_t)row * ldC + bn + warp_n * 64;
            const float* prow = (MODE == 1)
                ? (Cprev + (size_t)row * ldC + bn + warp_n * 64) : nullptr;
#pragma unroll
            for (int nt = 0; nt < 8; nt++) {
                float2 v;
                v.x = d[mt][nt][half * 2 + 0];
                v.y = d[mt][nt][half * 2 + 1];
                if (MODE == 1) {
                    float2 p = *(const float2*)(prow + nt * 8 + tig * 2);
                    v.x = 0.5f * (v.x + p.x);
                    v.y = 0.5f * (v.y + p.y);
                }
                *(float2*)(crow + nt * 8 + tig * 2) = v;
            }
        }
    }
}

// ---------------------------------------------------------------------------
// patterns (4096x1024) -> patT (1024x4096)
// ---------------------------------------------------------------------------
__global__ __launch_bounds__(256)
void transpose_kernel(const float* __restrict__ in, float* __restrict__ out)
{
    __shared__ float t[32][33];
    const int m0 = blockIdx.x * 32;
    const int c0 = blockIdx.y * 32;
    const int tx = threadIdx.x & 31;
    const int ty = threadIdx.x >> 5;   // 0..7
#pragma unroll
    for (int i = 0; i < 32; i += 8)
        t[ty + i][tx] = in[(size_t)(m0 + ty + i) * DIM_C + c0 + tx];
    __syncthreads();
#pragma unroll
    for (int i = 0; i < 32; i += 8)
        out[(size_t)(c0 + ty + i) * DIM_M + m0 + tx] = t[tx][ty + i];
}

// ---------------------------------------------------------------------------
// Row softmax over 4096 columns, one block per row, in place.
// ---------------------------------------------------------------------------
__global__ __launch_bounds__(256)
void softmax_kernel(float* __restrict__ S)
{
    const int ncols = DIM_M;
    __shared__ float red[8];
    float* p = S + (size_t)blockIdx.x * ncols;
    const int tid = threadIdx.x;
    const int lane = tid & 31, warp = tid >> 5;

    float m = -CUDART_INF_F;
    for (int c = tid * 4; c < ncols; c += 256 * 4) {
        float4 v = *(const float4*)&p[c];
        m = fmaxf(m, fmaxf(fmaxf(v.x, v.y), fmaxf(v.z, v.w)));
    }
#pragma unroll
    for (int o = 16; o > 0; o >>= 1) m = fmaxf(m, __shfl_xor_sync(0xffffffffu, m, o));
    if (lane == 0) red[warp] = m;
    __syncthreads();
    m = red[0];
#pragma unroll
    for (int w = 1; w < 8; w++) m = fmaxf(m, red[w]);
    __syncthreads();

    const float LOG2E = 1.4426950408889634f;
    float s = 0.0f;
    for (int c = tid * 4; c < ncols; c += 256 * 4) {
        float4 v = *(const float4*)&p[c];
        v.x = exp2f((v.x - m) * LOG2E);
        v.y = exp2f((v.y - m) * LOG2E);
        v.z = exp2f((v.z - m) * LOG2E);
        v.w = exp2f((v.w - m) * LOG2E);
        s += (v.x + v.y) + (v.z + v.w);
        *(float4*)&p[c] = v;
    }
#pragma unroll
    for (int o = 16; o > 0; o >>= 1) s += __shfl_xor_sync(0xffffffffu, s, o);
    if (lane == 0) red[warp] = s;
    __syncthreads();
    s = red[0];
#pragma unroll
    for (int w = 1; w < 8; w++) s += red[w];
    const float rinv = 1.0f / s;

    for (int c = tid * 4; c < ncols; c += 256 * 4) {
        float4 v = *(const float4*)&p[c];
        v.x *= rinv; v.y *= rinv; v.z *= rinv; v.w *= rinv;
        *(float4*)&p[c] = v;
    }
}

// ---------------------------------------------------------------------------
extern "C" void kernel_launch(void* const* d_in, const int* in_sizes, int n_in,
                              void* d_out, int out_size)
{
    (void)in_sizes; (void)n_in; (void)out_size;
    const float* x        = (const float*)d_in[0];   // 8192 x 1024
    const float* patterns = (const float*)d_in[1];   // 4096 x 1024
    const float* Wq       = (const float*)d_in[2];   // 1024 x 1024 (rows = out dim, K-major)
    const float* Wk       = (const float*)d_in[3];   // 1024 x 1024
    float* out = (float*)d_out;                      // 8192 x 1024

    float *state, *kmat, *sim, *patT;
    cudaGetSymbolAddress((void**)&state, g_state);
    cudaGetSymbolAddress((void**)&kmat,  g_k);
    cudaGetSymbolAddress((void**)&sim,   g_sim);
    cudaGetSymbolAddress((void**)&patT,  g_patT);

    cudaFuncSetAttribute(tc_gemm<0>, cudaFuncAttributeMaxDynamicSharedMemorySize, GEMM_SMEM);
    cudaFuncSetAttribute(tc_gemm<1>, cudaFuncAttributeMaxDynamicSharedMemorySize, GEMM_SMEM);

    dim3 blk(256);

    // q = x @ Wq^T -> state   (M=8192 rows, N=1024 cols, K=1024)
    tc_gemm<0><<<dim3(DIM_C / BN, ROWS_Q / BM), blk, GEMM_SMEM>>>(
        x, Wq, state, nullptr, DIM_C, DIM_C);

    // k = patterns @ Wk^T -> kmat  (4096 x 1024)
    tc_gemm<0><<<dim3(DIM_C / BN, DIM_M / BM), blk, GEMM_SMEM>>>(
        patterns, Wk, kmat, nullptr, DIM_C, DIM_C);

    // patT = patterns^T (1024 x 4096)
    transpose_kernel<<<dim3(DIM_M / 32, DIM_C / 32), dim3(256)>>>(patterns, patT);

    for (int it = 0; it < 4; it++) {
        // sim = state @ kmat^T  (8192 x 4096, K=1024)
        tc_gemm<0><<<dim3(DIM_M / BN, ROWS_Q / BM), blk, GEMM_SMEM>>>(
            state, kmat, sim, nullptr, DIM_C, DIM_M);

        softmax_kernel<<<ROWS_Q, dim3(256)>>>(sim);

        if (it < 3) {
            // state = 0.5*state + 0.5*(attn @ patterns) = blend(sim @ patT^T)
            tc_gemm<1><<<dim3(DIM_C / BN, ROWS_Q / BM), blk, GEMM_SMEM>>>(
                sim, patT, state, state, DIM_M, DIM_C);
        } else {
            tc_gemm<0><<<dim3(DIM_C / BN, ROWS_Q / BM), blk, GEMM_SMEM>>>(
                sim, patT, out, nullptr, DIM_M, DIM_C);
        }
    }
}

// round 6
// speedup vs baseline: 2.8123x; 1.1252x over previous
#include <cuda_runtime.h>
#include <math_constants.h>
#include <cstdint>

// Shapes (fixed): x 8192x1024, patterns 4096x1024, Wq/Wk 1024x1024
#define ROWS_Q 8192
#define DIM_C  1024
#define DIM_M  4096

// Scratch (__device__ globals; no allocations allowed)
__device__ float g_state[(size_t)ROWS_Q * DIM_C];   // 32 MB
__device__ float g_k[(size_t)DIM_M * DIM_C];        // 16 MB
__device__ float g_sim[(size_t)ROWS_Q * DIM_M];     // 128 MB
__device__ float g_patT[(size_t)DIM_C * DIM_M];     // 16 MB

// ---------------------------------------------------------------------------
// cp.async helpers (sm_80+, valid for compute_103 PTX target)
// ---------------------------------------------------------------------------
__device__ __forceinline__ uint32_t smem_u32(const void* p) {
    uint32_t a;
    asm("{ .reg .u64 t; cvta.to.shared.u64 t, %1; cvt.u32.u64 %0, t; }"
        : "=r"(a) : "l"(p));
    return a;
}
__device__ __forceinline__ void cpa16(uint32_t dst, const void* src) {
    asm volatile("cp.async.cg.shared.global [%0], [%1], 16;\n" :: "r"(dst), "l"(src));
}
__device__ __forceinline__ void cp_commit() {
    asm volatile("cp.async.commit_group;\n" ::: "memory");
}
template <int N>
__device__ __forceinline__ void cp_wait() {
    asm volatile("cp.async.wait_group %0;\n" :: "n"(N) : "memory");
}

__device__ __forceinline__ uint32_t f2tf32(float f) {
    uint32_t r;
    asm("cvt.rna.tf32.f32 %0, %1;\n" : "=r"(r) : "f"(f));
    return r;
}

// mma.sync m16n8k8 tf32: D(16x8,f32) += A(16x8,tf32) * B(8x8,tf32)
__device__ __forceinline__ void mma_tf32(float* d, const uint32_t* a, const uint32_t* b) {
    asm volatile(
        "mma.sync.aligned.m16n8k8.row.col.f32.tf32.tf32.f32 "
        "{%0,%1,%2,%3}, {%4,%5,%6,%7}, {%8,%9}, {%0,%1,%2,%3};\n"
        : "+f"(d[0]), "+f"(d[1]), "+f"(d[2]), "+f"(d[3])
        : "r"(a[0]), "r"(a[1]), "r"(a[2]), "r"(a[3]), "r"(b[0]), "r"(b[1]));
}

// ---------------------------------------------------------------------------
// tf32 tensor-core GEMM: C[m][n] = sum_k A[m][k] * B[n][k]
//   A: M x K (row-major), B: N x K (row-major), C: M x ldC
//   Block tile 128x128x32, 256 threads (8 warps: 4 along M x 2 along N).
//   Warp tile 32x64 = 2 (M) x 8 (N) mma tiles of 16x8.
//   3-stage cp.async pipeline, 2 CTAs/SM (16 warps/SM) for latency hiding.
//   MODE 0: C = D ; MODE 1: C = 0.5*Cprev + 0.5*D
//   smem rows padded to 36 floats (144B): conflict-free fills and frag loads.
// ---------------------------------------------------------------------------
#define BM 128
#define BN 128
#define BK 32
#define ROWF 36                              // floats per smem row (144 B)
#define STAGE_FLOATS (2 * 128 * ROWF)        // A tile + B tile = 9216 floats
#define STAGES 3
#define GEMM_SMEM (STAGES * STAGE_FLOATS * 4)   // 110592 B -> 2 CTAs/SM

template <int MODE>
__global__ __launch_bounds__(256, 2)
void tc_gemm(const float* __restrict__ A, const float* __restrict__ B,
             float* __restrict__ C, const float* __restrict__ Cprev,
             int K, int ldC)
{
    extern __shared__ float smem[];
    const int tid = threadIdx.x;
    const int wid = tid >> 5;
    const int lane = tid & 31;
    const int gid = lane >> 2;        // group id 0..7
    const int tig = lane & 3;         // thread-in-group 0..3
    const int warp_m = wid & 3;       // 0..3 -> 32-row band
    const int warp_n = wid >> 2;      // 0..1 -> 64-col band
    const int bm = blockIdx.y * BM;
    const int bn = blockIdx.x * BN;

    const uint32_t smem_b = smem_u32(smem);

    // ---- cooperative tile fill: 2048 x 16B chunks / 256 threads = 8 each
    auto load_tile = [&](int t, int s) {
        const uint32_t sb = smem_b + (uint32_t)s * (STAGE_FLOATS * 4);
        const int k0 = t * BK;
        const int r = tid >> 3;        // 0..31 base row
        const int j = tid & 7;         // chunk in row
#pragma unroll
        for (int p = 0; p < 4; p++) {  // A rows r, r+32, r+64, r+96
            const int row = r + 32 * p;
            cpa16(sb + row * 144 + j * 16, A + (size_t)(bm + row) * K + k0 + j * 4);
        }
#pragma unroll
        for (int p = 0; p < 4; p++) {  // B rows
            const int row = r + 32 * p;
            cpa16(sb + (128 + row) * 144 + j * 16, B + (size_t)(bn + row) * K + k0 + j * 4);
        }
        cp_commit();
    };

    float d[2][8][4];
#pragma unroll
    for (int mt = 0; mt < 2; mt++)
#pragma unroll
        for (int nt = 0; nt < 8; nt++)
#pragma unroll
            for (int i = 0; i < 4; i++) d[mt][nt][i] = 0.0f;

    const int T = K / BK;

    // prologue: 2 tiles in flight (3 stages)
    load_tile(0, 0);
    load_tile(1, 1);

    int s = 0;            // stage of tile t
    int s_load = 2;       // stage for tile t+2
    for (int t = 0; t < T; t++) {
        if (t < T - 1) cp_wait<1>();
        else cp_wait<0>();
        __syncthreads();   // tile t visible to all; prior compute on s_load done

        const int nt_load = t + 2;
        if (nt_load < T) load_tile(nt_load, s_load);

        const float* As = smem + s * STAGE_FLOATS;
        const float* Bs = As + 128 * ROWF;

#pragma unroll
        for (int ks = 0; ks < 4; ks++) {
            const int k0 = ks * 8;
            uint32_t a[2][4], b[8][2];
#pragma unroll
            for (int mt = 0; mt < 2; mt++) {
                const int m0 = warp_m * 32 + mt * 16;
                a[mt][0] = f2tf32(As[(m0 + gid)     * ROWF + k0 + tig]);
                a[mt][1] = f2tf32(As[(m0 + gid + 8) * ROWF + k0 + tig]);
                a[mt][2] = f2tf32(As[(m0 + gid)     * ROWF + k0 + tig + 4]);
                a[mt][3] = f2tf32(As[(m0 + gid + 8) * ROWF + k0 + tig + 4]);
            }
#pragma unroll
            for (int nt = 0; nt < 8; nt++) {
                const int n0 = warp_n * 64 + nt * 8;
                b[nt][0] = f2tf32(Bs[(n0 + gid) * ROWF + k0 + tig]);
                b[nt][1] = f2tf32(Bs[(n0 + gid) * ROWF + k0 + tig + 4]);
            }
#pragma unroll
            for (int mt = 0; mt < 2; mt++)
#pragma unroll
                for (int nt = 0; nt < 8; nt++)
                    mma_tf32(d[mt][nt], a[mt], b[nt]);
        }

        s = (s == STAGES - 1) ? 0 : s + 1;
        s_load = (s_load == STAGES - 1) ? 0 : s_load + 1;
    }

    // ---- epilogue: d regs -> C (float2 per fragment half-row)
#pragma unroll
    for (int mt = 0; mt < 2; mt++) {
        const int m0 = bm + warp_m * 32 + mt * 16 + gid;
#pragma unroll
        for (int half = 0; half < 2; half++) {
            const int row = m0 + half * 8;
            float* crow = C + (size_t)row * ldC + bn + warp_n * 64;
            const float* prow = (MODE == 1)
                ? (Cprev + (size_t)row * ldC + bn + warp_n * 64) : nullptr;
#pragma unroll
            for (int nt = 0; nt < 8; nt++) {
                float2 v;
                v.x = d[mt][nt][half * 2 + 0];
                v.y = d[mt][nt][half * 2 + 1];
                if (MODE == 1) {
                    float2 p = *(const float2*)(prow + nt * 8 + tig * 2);
                    v.x = 0.5f * (v.x + p.x);
                    v.y = 0.5f * (v.y + p.y);
                }
                *(float2*)(crow + nt * 8 + tig * 2) = v;
            }
        }
    }
}

// ---------------------------------------------------------------------------
// patterns (4096x1024) -> patT (1024x4096)
// ---------------------------------------------------------------------------
__global__ __launch_bounds__(256)
void transpose_kernel(const float* __restrict__ in, float* __restrict__ out)
{
    __shared__ float t[32][33];
    const int m0 = blockIdx.x * 32;
    const int c0 = blockIdx.y * 32;
    const int tx = threadIdx.x & 31;
    const int ty = threadIdx.x >> 5;   // 0..7
#pragma unroll
    for (int i = 0; i < 32; i += 8)
        t[ty + i][tx] = in[(size_t)(m0 + ty + i) * DIM_C + c0 + tx];
    __syncthreads();
#pragma unroll
    for (int i = 0; i < 32; i += 8)
        out[(size_t)(c0 + ty + i) * DIM_M + m0 + tx] = t[tx][ty + i];
}

// ---------------------------------------------------------------------------
// Row softmax over 4096 columns, one block per row, in place.
// ---------------------------------------------------------------------------
__global__ __launch_bounds__(256)
void softmax_kernel(float* __restrict__ S)
{
    const int ncols = DIM_M;
    __shared__ float red[8];
    float* p = S + (size_t)blockIdx.x * ncols;
    const int tid = threadIdx.x;
    const int lane = tid & 31, warp = tid >> 5;

    float m = -CUDART_INF_F;
    for (int c = tid * 4; c < ncols; c += 256 * 4) {
        float4 v = *(const float4*)&p[c];
        m = fmaxf(m, fmaxf(fmaxf(v.x, v.y), fmaxf(v.z, v.w)));
    }
#pragma unroll
    for (int o = 16; o > 0; o >>= 1) m = fmaxf(m, __shfl_xor_sync(0xffffffffu, m, o));
    if (lane == 0) red[warp] = m;
    __syncthreads();
    m = red[0];
#pragma unroll
    for (int w = 1; w < 8; w++) m = fmaxf(m, red[w]);
    __syncthreads();

    const float LOG2E = 1.4426950408889634f;
    float s = 0.0f;
    for (int c = tid * 4; c < ncols; c += 256 * 4) {
        float4 v = *(const float4*)&p[c];
        v.x = exp2f((v.x - m) * LOG2E);
        v.y = exp2f((v.y - m) * LOG2E);
        v.z = exp2f((v.z - m) * LOG2E);
        v.w = exp2f((v.w - m) * LOG2E);
        s += (v.x + v.y) + (v.z + v.w);
        *(float4*)&p[c] = v;
    }
#pragma unroll
    for (int o = 16; o > 0; o >>= 1) s += __shfl_xor_sync(0xffffffffu, s, o);
    if (lane == 0) red[warp] = s;
    __syncthreads();
    s = red[0];
#pragma unroll
    for (int w = 1; w < 8; w++) s += red[w];
    const float rinv = 1.0f / s;

    for (int c = tid * 4; c < ncols; c += 256 * 4) {
        float4 v = *(const float4*)&p[c];
        v.x *= rinv; v.y *= rinv; v.z *= rinv; v.w *= rinv;
        *(float4*)&p[c] = v;
    }
}

// ---------------------------------------------------------------------------
extern "C" void kernel_launch(void* const* d_in, const int* in_sizes, int n_in,
                              void* d_out, int out_size)
{
    (void)in_sizes; (void)n_in; (void)out_size;
    const float* x        = (const float*)d_in[0];   // 8192 x 1024
    const float* patterns = (const float*)d_in[1];   // 4096 x 1024
    const float* Wq       = (const float*)d_in[2];   // 1024 x 1024 (rows = out dim, K-major)
    const float* Wk       = (const float*)d_in[3];   // 1024 x 1024
    float* out = (float*)d_out;                      // 8192 x 1024

    float *state, *kmat, *sim, *patT;
    cudaGetSymbolAddress((void**)&state, g_state);
    cudaGetSymbolAddress((void**)&kmat,  g_k);
    cudaGetSymbolAddress((void**)&sim,   g_sim);
    cudaGetSymbolAddress((void**)&patT,  g_patT);

    cudaFuncSetAttribute(tc_gemm<0>, cudaFuncAttributeMaxDynamicSharedMemorySize, GEMM_SMEM);
    cudaFuncSetAttribute(tc_gemm<1>, cudaFuncAttributeMaxDynamicSharedMemorySize, GEMM_SMEM);

    dim3 blk(256);

    // q = x @ Wq^T -> state   (M=8192 rows, N=1024 cols, K=1024)
    tc_gemm<0><<<dim3(DIM_C / BN, ROWS_Q / BM), blk, GEMM_SMEM>>>(
        x, Wq, state, nullptr, DIM_C, DIM_C);

    // k = patterns @ Wk^T -> kmat  (4096 x 1024)
    tc_gemm<0><<<dim3(DIM_C / BN, DIM_M / BM), blk, GEMM_SMEM>>>(
        patterns, Wk, kmat, nullptr, DIM_C, DIM_C);

    // patT = patterns^T (1024 x 4096)
    transpose_kernel<<<dim3(DIM_M / 32, DIM_C / 32), dim3(256)>>>(patterns, patT);

    for (int it = 0; it < 4; it++) {
        // sim = state @ kmat^T  (8192 x 4096, K=1024)
        tc_gemm<0><<<dim3(DIM_M / BN, ROWS_Q / BM), blk, GEMM_SMEM>>>(
            state, kmat, sim, nullptr, DIM_C, DIM_M);

        softmax_kernel<<<ROWS_Q, dim3(256)>>>(sim);

        if (it < 3) {
            // state = 0.5*state + 0.5*(attn @ patterns) = blend(sim @ patT^T)
            tc_gemm<1><<<dim3(DIM_C / BN, ROWS_Q / BM), blk, GEMM_SMEM>>>(
                sim, patT, state, state, DIM_M, DIM_C);
        } else {
            tc_gemm<0><<<dim3(DIM_C / BN, ROWS_Q / BM), blk, GEMM_SMEM>>>(
                sim, patT, out, nullptr, DIM_M, DIM_C);
        }
    }
}

// round 7
// speedup vs baseline: 7.3417x; 2.6106x over previous
#include <cuda_runtime.h>
#include <cuda_fp16.h>
#include <math_constants.h>
#include <cstdint>

// Shapes (fixed): x 8192x1024, patterns 4096x1024, Wq/Wk 1024x1024
#define ROWS_Q 8192
#define DIM_C  1024
#define DIM_M  4096

// Scratch (__device__ globals; no allocations allowed)
__device__ float  g_state[(size_t)ROWS_Q * DIM_C];   // 32 MB fp32 master
__device__ __half g_stateh[(size_t)ROWS_Q * DIM_C];  // 16 MB fp16 mirror
__device__ __half g_kh[(size_t)DIM_M * DIM_C];       // 8 MB
__device__ float  g_sim[(size_t)ROWS_Q * DIM_M];     // 128 MB logits fp32
__device__ __half g_attnh[(size_t)ROWS_Q * DIM_M];   // 64 MB
__device__ __half g_patTh[(size_t)DIM_C * DIM_M];    // 8 MB
__device__ __half g_xh[(size_t)ROWS_Q * DIM_C];      // 16 MB
__device__ __half g_path[(size_t)DIM_M * DIM_C];     // 8 MB
__device__ __half g_wqh[(size_t)DIM_C * DIM_C];      // 2 MB
__device__ __half g_wkh[(size_t)DIM_C * DIM_C];      // 2 MB

// ---------------------------------------------------------------------------
// PTX helpers (all sm_75/sm_80-era, valid for compute_103 target)
// ---------------------------------------------------------------------------
__device__ __forceinline__ uint32_t smem_u32(const void* p) {
    uint32_t a;
    asm("{ .reg .u64 t; cvta.to.shared.u64 t, %1; cvt.u32.u64 %0, t; }"
        : "=r"(a) : "l"(p));
    return a;
}
__device__ __forceinline__ void cpa16(uint32_t dst, const void* src) {
    asm volatile("cp.async.cg.shared.global [%0], [%1], 16;\n" :: "r"(dst), "l"(src));
}
__device__ __forceinline__ void cp_commit() {
    asm volatile("cp.async.commit_group;\n" ::: "memory");
}
template <int N>
__device__ __forceinline__ void cp_wait() {
    asm volatile("cp.async.wait_group %0;\n" :: "n"(N) : "memory");
}
__device__ __forceinline__ void ldm_x4(uint32_t& r0, uint32_t& r1,
                                       uint32_t& r2, uint32_t& r3, uint32_t addr) {
    asm volatile("ldmatrix.sync.aligned.m8n8.x4.shared.b16 {%0,%1,%2,%3}, [%4];"
                 : "=r"(r0), "=r"(r1), "=r"(r2), "=r"(r3) : "r"(addr));
}
// D(16x8,f32) += A(16x16,f16) * B(16x8,f16)
__device__ __forceinline__ void mma_f16(float* d, const uint32_t* a, const uint32_t* b) {
    asm volatile(
        "mma.sync.aligned.m16n8k16.row.col.f32.f16.f16.f32 "
        "{%0,%1,%2,%3}, {%4,%5,%6,%7}, {%8,%9}, {%0,%1,%2,%3};\n"
        : "+f"(d[0]), "+f"(d[1]), "+f"(d[2]), "+f"(d[3])
        : "r"(a[0]), "r"(a[1]), "r"(a[2]), "r"(a[3]), "r"(b[0]), "r"(b[1]));
}

// ---------------------------------------------------------------------------
// fp16 tensor-core GEMM, fp32 accumulate: C[m][n] = sum_k A[m][k]*B[n][k]
//   A: M x K (half, K-major), B: N x K (half, K-major)
//   Block tile 128x128x64(halves), 128 threads (4 warps, 2x2), warp tile 64x64.
//   SW128 chunk-xor swizzle; cp.async fills; ldmatrix fragment loads.
//   3-stage pipeline; 2 CTAs/SM by smem (96 KB each).
//   MODE 0: C32 = D
//   MODE 1: C32 = D,              C16 = D
//   MODE 2: C32 = .5*(Cprev + D), C16 = same  (state update)
//   MODE 3: C16 = D
// ---------------------------------------------------------------------------
#define BK_H 64                               // halves per k-tile (128 B rows)
#define STAGE_BYTES_H (2 * 128 * 128)         // A tile 16KB + B tile 16KB
#define STAGES_H 3
#define GEMM_SMEM_H (STAGES_H * STAGE_BYTES_H)   // 98304 B

template <int MODE>
__global__ __launch_bounds__(128)
void hgemm(const __half* __restrict__ A, const __half* __restrict__ B,
           float* __restrict__ C32, __half* __restrict__ C16,
           const float* __restrict__ Cprev, int K, int ldC)
{
    extern __shared__ char smemc[];
    const uint32_t sb0 = smem_u32(smemc);
    const int tid = threadIdx.x;
    const int lane = tid & 31;
    const int wid = tid >> 5;
    const int warp_m = wid & 1;     // 2 warp rows  -> 64 M-rows each
    const int warp_n = wid >> 1;    // 2 warp cols  -> 64 N-cols each
    const int bm = blockIdx.y * 128;
    const int bn = blockIdx.x * 128;

    // cooperative fill: 128 rows x 8 chunks (16B) per operand tile
    auto load_tile = [&](int t, int s) {
        const uint32_t sbA = sb0 + (uint32_t)s * STAGE_BYTES_H;
        const uint32_t sbB = sbA + 128 * 128;
        const int k0 = t * BK_H;
        const int c = tid & 7;
        const int rbase = tid >> 3;            // 0..15
#pragma unroll
        for (int p = 0; p < 8; p++) {
            const int r = rbase + 16 * p;
            cpa16(sbA + r * 128 + ((c ^ (r & 7)) << 4),
                  A + (size_t)(bm + r) * K + k0 + c * 8);
        }
#pragma unroll
        for (int p = 0; p < 8; p++) {
            const int r = rbase + 16 * p;
            cpa16(sbB + r * 128 + ((c ^ (r & 7)) << 4),
                  B + (size_t)(bn + r) * K + k0 + c * 8);
        }
        cp_commit();
    };

    float d[4][8][4];
#pragma unroll
    for (int mt = 0; mt < 4; mt++)
#pragma unroll
        for (int nt = 0; nt < 8; nt++)
#pragma unroll
            for (int i = 0; i < 4; i++) d[mt][nt][i] = 0.0f;

    // per-lane ldmatrix address components
    const int ra = ((lane >> 3) & 1) * 8 + (lane & 7);   // A row-in-16, tiles {m,m+8}x{k,k+8}
    const int ka = (lane >> 4) & 1;                      // A k-chunk offset
    const int rb = ((lane >> 4) & 1) * 8 + (lane & 7);   // B row-in-16, tiles {k,k+8}x{n,n+8}
    const int kb = (lane >> 3) & 1;

    const int T = K / BK_H;
    load_tile(0, 0);
    load_tile(1, 1);

    int s = 0, sl = 2;
    for (int t = 0; t < T; t++) {
        if (t < T - 1) cp_wait<1>();
        else cp_wait<0>();
        __syncthreads();

        if (t + 2 < T) load_tile(t + 2, sl);

        const uint32_t sbA = sb0 + (uint32_t)s * STAGE_BYTES_H;
        const uint32_t sbB = sbA + 128 * 128;

#pragma unroll
        for (int ks = 0; ks < 4; ks++) {
            const int kc = ks * 2;     // 16 halves = 2 chunks per kstep
            uint32_t a[4][4], b[8][2];
#pragma unroll
            for (int mt = 0; mt < 4; mt++) {
                const int row = warp_m * 64 + mt * 16 + ra;
                ldm_x4(a[mt][0], a[mt][1], a[mt][2], a[mt][3],
                       sbA + row * 128 + (((kc + ka) ^ (ra & 7)) << 4));
            }
#pragma unroll
            for (int np = 0; np < 4; np++) {
                const int row = warp_n * 64 + np * 16 + rb;
                ldm_x4(b[2 * np][0], b[2 * np][1], b[2 * np + 1][0], b[2 * np + 1][1],
                       sbB + row * 128 + (((kc + kb) ^ (rb & 7)) << 4));
            }
#pragma unroll
            for (int mt = 0; mt < 4; mt++)
#pragma unroll
                for (int nt = 0; nt < 8; nt++)
                    mma_f16(d[mt][nt], a[mt], b[nt]);
        }
        s = (s == 2) ? 0 : s + 1;
        sl = (sl == 2) ? 0 : sl + 1;
    }

    // epilogue
    const int gidl = lane >> 2, tig = lane & 3;
#pragma unroll
    for (int mt = 0; mt < 4; mt++) {
#pragma unroll
        for (int hf = 0; hf < 2; hf++) {
            const int row = bm + warp_m * 64 + mt * 16 + gidl + hf * 8;
            const size_t roff = (size_t)row * ldC + bn + warp_n * 64;
#pragma unroll
            for (int nt = 0; nt < 8; nt++) {
                float vx = d[mt][nt][hf * 2 + 0];
                float vy = d[mt][nt][hf * 2 + 1];
                const int coff = nt * 8 + tig * 2;
                if (MODE == 2) {
                    float2 p = *(const float2*)(Cprev + roff + coff);
                    vx = 0.5f * (vx + p.x);
                    vy = 0.5f * (vy + p.y);
                }
                if (MODE == 0 || MODE == 1 || MODE == 2) {
                    float2 o; o.x = vx; o.y = vy;
                    *(float2*)(C32 + roff + coff) = o;
                }
                if (MODE == 1 || MODE == 2 || MODE == 3) {
                    *(__half2*)(C16 + roff + coff) = __floats2half2_rn(vx, vy);
                }
            }
        }
    }
}

// ---------------------------------------------------------------------------
// fp32 -> fp16 elementwise convert (n multiple of 4)
// ---------------------------------------------------------------------------
__global__ __launch_bounds__(256)
void f2h_kernel(const float* __restrict__ in, __half* __restrict__ out, int n)
{
    int i = (blockIdx.x * 256 + threadIdx.x) * 4;
    if (i < n) {
        float4 v = *(const float4*)(in + i);
        *(__half2*)(out + i)     = __floats2half2_rn(v.x, v.y);
        *(__half2*)(out + i + 2) = __floats2half2_rn(v.z, v.w);
    }
}

// ---------------------------------------------------------------------------
// patterns (4096x1024 fp32) -> patT (1024x4096 fp16)
// ---------------------------------------------------------------------------
__global__ __launch_bounds__(256)
void transpose_h_kernel(const float* __restrict__ in, __half* __restrict__ out)
{
    __shared__ float t[32][33];
    const int m0 = blockIdx.x * 32;
    const int c0 = blockIdx.y * 32;
    const int tx = threadIdx.x & 31;
    const int ty = threadIdx.x >> 5;
#pragma unroll
    for (int i = 0; i < 32; i += 8)
        t[ty + i][tx] = in[(size_t)(m0 + ty + i) * DIM_C + c0 + tx];
    __syncthreads();
#pragma unroll
    for (int i = 0; i < 32; i += 8)
        out[(size_t)(c0 + ty + i) * DIM_M + m0 + tx] = __float2half(t[tx][ty + i]);
}

// ---------------------------------------------------------------------------
// Row softmax: read fp32 logits (register-resident), write fp16 attn.
// 4096 cols, 256 threads, 16 elems/thread.
// ---------------------------------------------------------------------------
__global__ __launch_bounds__(256)
void softmax_h_kernel(const float* __restrict__ S, __half* __restrict__ Ah)
{
    __shared__ float red[8];
    const float* p = S + (size_t)blockIdx.x * DIM_M;
    __half* q = Ah + (size_t)blockIdx.x * DIM_M;
    const int tid = threadIdx.x;
    const int lane = tid & 31, warp = tid >> 5;

    float4 v[4];
    float m = -CUDART_INF_F;
#pragma unroll
    for (int i = 0; i < 4; i++) {
        v[i] = *(const float4*)(p + tid * 4 + i * 1024);
        m = fmaxf(m, fmaxf(fmaxf(v[i].x, v[i].y), fmaxf(v[i].z, v[i].w)));
    }
#pragma unroll
    for (int o = 16; o > 0; o >>= 1) m = fmaxf(m, __shfl_xor_sync(0xffffffffu, m, o));
    if (lane == 0) red[warp] = m;
    __syncthreads();
    m = red[0];
#pragma unroll
    for (int w = 1; w < 8; w++) m = fmaxf(m, red[w]);
    __syncthreads();

    const float LOG2E = 1.4426950408889634f;
    float sum = 0.0f;
#pragma unroll
    for (int i = 0; i < 4; i++) {
        v[i].x = exp2f((v[i].x - m) * LOG2E);
        v[i].y = exp2f((v[i].y - m) * LOG2E);
        v[i].z = exp2f((v[i].z - m) * LOG2E);
        v[i].w = exp2f((v[i].w - m) * LOG2E);
        sum += (v[i].x + v[i].y) + (v[i].z + v[i].w);
    }
#pragma unroll
    for (int o = 16; o > 0; o >>= 1) sum += __shfl_xor_sync(0xffffffffu, sum, o);
    if (lane == 0) red[warp] = sum;
    __syncthreads();
    sum = red[0];
#pragma unroll
    for (int w = 1; w < 8; w++) sum += red[w];
    const float r = 1.0f / sum;

#pragma unroll
    for (int i = 0; i < 4; i++) {
        __half* qo = q + tid * 4 + i * 1024;
        *(__half2*)(qo)     = __floats2half2_rn(v[i].x * r, v[i].y * r);
        *(__half2*)(qo + 2) = __floats2half2_rn(v[i].z * r, v[i].w * r);
    }
}

// ---------------------------------------------------------------------------
extern "C" void kernel_launch(void* const* d_in, const int* in_sizes, int n_in,
                              void* d_out, int out_size)
{
    (void)in_sizes; (void)n_in; (void)out_size;
    const float* x        = (const float*)d_in[0];   // 8192 x 1024
    const float* patterns = (const float*)d_in[1];   // 4096 x 1024
    const float* Wq       = (const float*)d_in[2];   // 1024 x 1024
    const float* Wk       = (const float*)d_in[3];   // 1024 x 1024
    float* out = (float*)d_out;                      // 8192 x 1024

    float *state, *sim;
    __half *stateh, *kh, *attnh, *patTh, *xh, *path, *wqh, *wkh;
    cudaGetSymbolAddress((void**)&state,  g_state);
    cudaGetSymbolAddress((void**)&stateh, g_stateh);
    cudaGetSymbolAddress((void**)&kh,     g_kh);
    cudaGetSymbolAddress((void**)&sim,    g_sim);
    cudaGetSymbolAddress((void**)&attnh,  g_attnh);
    cudaGetSymbolAddress((void**)&patTh,  g_patTh);
    cudaGetSymbolAddress((void**)&xh,     g_xh);
    cudaGetSymbolAddress((void**)&path,   g_path);
    cudaGetSymbolAddress((void**)&wqh,    g_wqh);
    cudaGetSymbolAddress((void**)&wkh,    g_wkh);

    cudaFuncSetAttribute(hgemm<0>, cudaFuncAttributeMaxDynamicSharedMemorySize, GEMM_SMEM_H);
    cudaFuncSetAttribute(hgemm<1>, cudaFuncAttributeMaxDynamicSharedMemorySize, GEMM_SMEM_H);
    cudaFuncSetAttribute(hgemm<2>, cudaFuncAttributeMaxDynamicSharedMemorySize, GEMM_SMEM_H);
    cudaFuncSetAttribute(hgemm<3>, cudaFuncAttributeMaxDynamicSharedMemorySize, GEMM_SMEM_H);

    dim3 blk(128);

    // one-time fp16 conversions
    f2h_kernel<<<(ROWS_Q * DIM_C) / 1024, 256>>>(x, xh, ROWS_Q * DIM_C);
    f2h_kernel<<<(DIM_M * DIM_C) / 1024, 256>>>(patterns, path, DIM_M * DIM_C);
    f2h_kernel<<<(DIM_C * DIM_C) / 1024, 256>>>(Wq, wqh, DIM_C * DIM_C);
    f2h_kernel<<<(DIM_C * DIM_C) / 1024, 256>>>(Wk, wkh, DIM_C * DIM_C);
    transpose_h_kernel<<<dim3(DIM_M / 32, DIM_C / 32), dim3(256)>>>(patterns, patTh);

    // q = x @ Wq^T -> state(fp32) + stateh(fp16)
    hgemm<1><<<dim3(DIM_C / 128, ROWS_Q / 128), blk, GEMM_SMEM_H>>>(
        xh, wqh, state, stateh, nullptr, DIM_C, DIM_C);

    // k = patterns @ Wk^T -> kh (fp16 only)
    hgemm<3><<<dim3(DIM_C / 128, DIM_M / 128), blk, GEMM_SMEM_H>>>(
        path, wkh, nullptr, kh, nullptr, DIM_C, DIM_C);

    for (int it = 0; it < 4; it++) {
        // sim = state @ k^T (fp32 logits)
        hgemm<0><<<dim3(DIM_M / 128, ROWS_Q / 128), blk, GEMM_SMEM_H>>>(
            stateh, kh, sim, nullptr, nullptr, DIM_C, DIM_M);

        softmax_h_kernel<<<ROWS_Q, dim3(256)>>>(sim, attnh);

        if (it < 3) {
            // state = 0.5*state + 0.5*(attn @ patterns)
            hgemm<2><<<dim3(DIM_C / 128, ROWS_Q / 128), blk, GEMM_SMEM_H>>>(
                attnh, patTh, state, stateh, state, DIM_M, DIM_C);
        } else {
            hgemm<0><<<dim3(DIM_C / 128, ROWS_Q / 128), blk, GEMM_SMEM_H>>>(
                attnh, patTh, out, nullptr, nullptr, DIM_M, DIM_C);
        }
    }
}

// round 8
// speedup vs baseline: 7.7473x; 1.0552x over previous
#include <cuda_runtime.h>
#include <cuda_fp16.h>
#include <math_constants.h>
#include <cstdint>

// Shapes (fixed): x 8192x1024, patterns 4096x1024, Wq/Wk 1024x1024
#define ROWS_Q 8192
#define DIM_C  1024
#define DIM_M  4096

// Scratch (__device__ globals; no allocations allowed)
__device__ __half g_stateh[(size_t)ROWS_Q * DIM_C];  // 16 MB (fp16 state)
__device__ __half g_kh[(size_t)DIM_M * DIM_C];       // 8 MB
__device__ float  g_sim[(size_t)ROWS_Q * DIM_M];     // 128 MB logits fp32
__device__ __half g_attnh[(size_t)ROWS_Q * DIM_M];   // 64 MB
__device__ __half g_patTh[(size_t)DIM_C * DIM_M];    // 8 MB
__device__ __half g_xh[(size_t)ROWS_Q * DIM_C];      // 16 MB
__device__ __half g_path[(size_t)DIM_M * DIM_C];     // 8 MB
__device__ __half g_wqh[(size_t)DIM_C * DIM_C];      // 2 MB
__device__ __half g_wkh[(size_t)DIM_C * DIM_C];      // 2 MB

// ---------------------------------------------------------------------------
// PTX helpers (sm_75/sm_80-era, valid for compute_103 target)
// ---------------------------------------------------------------------------
__device__ __forceinline__ uint32_t smem_u32(const void* p) {
    uint32_t a;
    asm("{ .reg .u64 t; cvta.to.shared.u64 t, %1; cvt.u32.u64 %0, t; }"
        : "=r"(a) : "l"(p));
    return a;
}
__device__ __forceinline__ void cpa16(uint32_t dst, const void* src) {
    asm volatile("cp.async.cg.shared.global [%0], [%1], 16;\n" :: "r"(dst), "l"(src));
}
__device__ __forceinline__ void cp_commit() {
    asm volatile("cp.async.commit_group;\n" ::: "memory");
}
template <int N>
__device__ __forceinline__ void cp_wait() {
    asm volatile("cp.async.wait_group %0;\n" :: "n"(N) : "memory");
}
__device__ __forceinline__ void ldm_x4(uint32_t& r0, uint32_t& r1,
                                       uint32_t& r2, uint32_t& r3, uint32_t addr) {
    asm volatile("ldmatrix.sync.aligned.m8n8.x4.shared.b16 {%0,%1,%2,%3}, [%4];"
                 : "=r"(r0), "=r"(r1), "=r"(r2), "=r"(r3) : "r"(addr));
}
// D(16x8,f32) += A(16x16,f16) * B(16x8,f16)
__device__ __forceinline__ void mma_f16(float* d, const uint32_t* a, const uint32_t* b) {
    asm volatile(
        "mma.sync.aligned.m16n8k16.row.col.f32.f16.f16.f32 "
        "{%0,%1,%2,%3}, {%4,%5,%6,%7}, {%8,%9}, {%0,%1,%2,%3};\n"
        : "+f"(d[0]), "+f"(d[1]), "+f"(d[2]), "+f"(d[3])
        : "r"(a[0]), "r"(a[1]), "r"(a[2]), "r"(a[3]), "r"(b[0]), "r"(b[1]));
}

// ---------------------------------------------------------------------------
// fp16 tensor-core GEMM, fp32 accumulate: C[m][n] = sum_k A[m][k]*B[n][k]
//   A: M x K (half, K-major), B: N x K (half, K-major)
//   Block tile 128x128x64(halves), 128 threads (4 warps, 2x2), warp tile 64x64.
//   SW128 chunk-xor swizzle; cp.async fills; ldmatrix fragment loads.
//   2-stage pipeline; 3 CTAs/SM (192 KB smem, 12 warps/SM).
//   MODE 0: C32 = D
//   MODE 3: C16 = D
//   MODE 4: C16 = 0.5*(Cprev16 + D)   (fp16 state blend)
// ---------------------------------------------------------------------------
#define BK_H 64                               // halves per k-tile (128 B rows)
#define STAGE_BYTES_H (2 * 128 * 128)         // A tile 16KB + B tile 16KB
#define STAGES_H 2
#define GEMM_SMEM_H (STAGES_H * STAGE_BYTES_H)   // 65536 B -> 3 CTAs/SM

template <int MODE>
__global__ __launch_bounds__(128, 3)
void hgemm(const __half* __restrict__ A, const __half* __restrict__ B,
           float* __restrict__ C32, __half* __restrict__ C16,
           const __half* __restrict__ Cprev16, int K, int ldC)
{
    extern __shared__ char smemc[];
    const uint32_t sb0 = smem_u32(smemc);
    const int tid = threadIdx.x;
    const int lane = tid & 31;
    const int wid = tid >> 5;
    const int warp_m = wid & 1;     // 2 warp rows  -> 64 M-rows each
    const int warp_n = wid >> 1;    // 2 warp cols  -> 64 N-cols each
    const int bm = blockIdx.y * 128;
    const int bn = blockIdx.x * 128;

    // cooperative fill: 128 rows x 8 chunks (16B) per operand tile
    auto load_tile = [&](int t, int s) {
        const uint32_t sbA = sb0 + (uint32_t)s * STAGE_BYTES_H;
        const uint32_t sbB = sbA + 128 * 128;
        const int k0 = t * BK_H;
        const int c = tid & 7;
        const int rbase = tid >> 3;            // 0..15
#pragma unroll
        for (int p = 0; p < 8; p++) {
            const int r = rbase + 16 * p;
            cpa16(sbA + r * 128 + ((c ^ (r & 7)) << 4),
                  A + (size_t)(bm + r) * K + k0 + c * 8);
        }
#pragma unroll
        for (int p = 0; p < 8; p++) {
            const int r = rbase + 16 * p;
            cpa16(sbB + r * 128 + ((c ^ (r & 7)) << 4),
                  B + (size_t)(bn + r) * K + k0 + c * 8);
        }
        cp_commit();
    };

    float d[4][8][4];
#pragma unroll
    for (int mt = 0; mt < 4; mt++)
#pragma unroll
        for (int nt = 0; nt < 8; nt++)
#pragma unroll
            for (int i = 0; i < 4; i++) d[mt][nt][i] = 0.0f;

    // per-lane ldmatrix address components
    const int ra = ((lane >> 3) & 1) * 8 + (lane & 7);   // A row-in-16
    const int ka = (lane >> 4) & 1;                      // A k-chunk offset
    const int rb = ((lane >> 4) & 1) * 8 + (lane & 7);   // B row-in-16
    const int kb = (lane >> 3) & 1;

    const int T = K / BK_H;
    load_tile(0, 0);
    load_tile(1, 1);

    int s = 0;
    for (int t = 0; t < T; t++) {
        if (t < T - 1) cp_wait<1>();
        else cp_wait<0>();
        __syncthreads();

        const uint32_t sbA = sb0 + (uint32_t)s * STAGE_BYTES_H;
        const uint32_t sbB = sbA + 128 * 128;

#pragma unroll
        for (int ks = 0; ks < 4; ks++) {
            const int kc = ks * 2;     // 16 halves = 2 chunks per kstep
            uint32_t a[4][4], b[8][2];
#pragma unroll
            for (int mt = 0; mt < 4; mt++) {
                const int row = warp_m * 64 + mt * 16 + ra;
                ldm_x4(a[mt][0], a[mt][1], a[mt][2], a[mt][3],
                       sbA + row * 128 + (((kc + ka) ^ (ra & 7)) << 4));
            }
#pragma unroll
            for (int np = 0; np < 4; np++) {
                const int row = warp_n * 64 + np * 16 + rb;
                ldm_x4(b[2 * np][0], b[2 * np][1], b[2 * np + 1][0], b[2 * np + 1][1],
                       sbB + row * 128 + (((kc + kb) ^ (rb & 7)) << 4));
            }
#pragma unroll
            for (int mt = 0; mt < 4; mt++)
#pragma unroll
                for (int nt = 0; nt < 8; nt++)
                    mma_f16(d[mt][nt], a[mt], b[nt]);
        }

        __syncthreads();                 // stage s fully consumed
        if (t + 2 < T) load_tile(t + 2, s);
        s ^= 1;
    }

    // epilogue
    const int gidl = lane >> 2, tig = lane & 3;
#pragma unroll
    for (int mt = 0; mt < 4; mt++) {
#pragma unroll
        for (int hf = 0; hf < 2; hf++) {
            const int row = bm + warp_m * 64 + mt * 16 + gidl + hf * 8;
            const size_t roff = (size_t)row * ldC + bn + warp_n * 64;
#pragma unroll
            for (int nt = 0; nt < 8; nt++) {
                float vx = d[mt][nt][hf * 2 + 0];
                float vy = d[mt][nt][hf * 2 + 1];
                const int coff = nt * 8 + tig * 2;
                if (MODE == 0) {
                    float2 o; o.x = vx; o.y = vy;
                    *(float2*)(C32 + roff + coff) = o;
                } else if (MODE == 3) {
                    *(__half2*)(C16 + roff + coff) = __floats2half2_rn(vx, vy);
                } else {   // MODE 4: fp16 state blend
                    __half2 ph = *(const __half2*)(Cprev16 + roff + coff);
                    float2 p = __half22float2(ph);
                    vx = 0.5f * (vx + p.x);
                    vy = 0.5f * (vy + p.y);
                    *(__half2*)(C16 + roff + coff) = __floats2half2_rn(vx, vy);
                }
            }
        }
    }
}

// ---------------------------------------------------------------------------
// fp32 -> fp16 elementwise convert (n multiple of 4)
// ---------------------------------------------------------------------------
__global__ __launch_bounds__(256)
void f2h_kernel(const float* __restrict__ in, __half* __restrict__ out, int n)
{
    int i = (blockIdx.x * 256 + threadIdx.x) * 4;
    if (i < n) {
        float4 v = *(const float4*)(in + i);
        *(__half2*)(out + i)     = __floats2half2_rn(v.x, v.y);
        *(__half2*)(out + i + 2) = __floats2half2_rn(v.z, v.w);
    }
}

// ---------------------------------------------------------------------------
// patterns (4096x1024 fp32) -> patT (1024x4096 fp16)
// ---------------------------------------------------------------------------
__global__ __launch_bounds__(256)
void transpose_h_kernel(const float* __restrict__ in, __half* __restrict__ out)
{
    __shared__ float t[32][33];
    const int m0 = blockIdx.x * 32;
    const int c0 = blockIdx.y * 32;
    const int tx = threadIdx.x & 31;
    const int ty = threadIdx.x >> 5;
#pragma unroll
    for (int i = 0; i < 32; i += 8)
        t[ty + i][tx] = in[(size_t)(m0 + ty + i) * DIM_C + c0 + tx];
    __syncthreads();
#pragma unroll
    for (int i = 0; i < 32; i += 8)
        out[(size_t)(c0 + ty + i) * DIM_M + m0 + tx] = __float2half(t[tx][ty + i]);
}

// ---------------------------------------------------------------------------
// Row softmax: read fp32 logits (register-resident), write fp16 attn.
// 4096 cols, 256 threads, 16 elems/thread.
// ---------------------------------------------------------------------------
__global__ __launch_bounds__(256)
void softmax_h_kernel(const float* __restrict__ S, __half* __restrict__ Ah)
{
    __shared__ float red[8];
    const float* p = S + (size_t)blockIdx.x * DIM_M;
    __half* q = Ah + (size_t)blockIdx.x * DIM_M;
    const int tid = threadIdx.x;
    const int lane = tid & 31, warp = tid >> 5;

    float4 v[4];
    float m = -CUDART_INF_F;
#pragma unroll
    for (int i = 0; i < 4; i++) {
        v[i] = *(const float4*)(p + tid * 4 + i * 1024);
        m = fmaxf(m, fmaxf(fmaxf(v[i].x, v[i].y), fmaxf(v[i].z, v[i].w)));
    }
#pragma unroll
    for (int o = 16; o > 0; o >>= 1) m = fmaxf(m, __shfl_xor_sync(0xffffffffu, m, o));
    if (lane == 0) red[warp] = m;
    __syncthreads();
    m = red[0];
#pragma unroll
    for (int w = 1; w < 8; w++) m = fmaxf(m, red[w]);
    __syncthreads();

    const float LOG2E = 1.4426950408889634f;
    float sum = 0.0f;
#pragma unroll
    for (int i = 0; i < 4; i++) {
        v[i].x = exp2f((v[i].x - m) * LOG2E);
        v[i].y = exp2f((v[i].y - m) * LOG2E);
        v[i].z = exp2f((v[i].z - m) * LOG2E);
        v[i].w = exp2f((v[i].w - m) * LOG2E);
        sum += (v[i].x + v[i].y) + (v[i].z + v[i].w);
    }
#pragma unroll
    for (int o = 16; o > 0; o >>= 1) sum += __shfl_xor_sync(0xffffffffu, sum, o);
    if (lane == 0) red[warp] = sum;
    __syncthreads();
    sum = red[0];
#pragma unroll
    for (int w = 1; w < 8; w++) sum += red[w];
    const float r = 1.0f / sum;

#pragma unroll
    for (int i = 0; i < 4; i++) {
        __half* qo = q + tid * 4 + i * 1024;
        *(__half2*)(qo)     = __floats2half2_rn(v[i].x * r, v[i].y * r);
        *(__half2*)(qo + 2) = __floats2half2_rn(v[i].z * r, v[i].w * r);
    }
}

// ---------------------------------------------------------------------------
extern "C" void kernel_launch(void* const* d_in, const int* in_sizes, int n_in,
                              void* d_out, int out_size)
{
    (void)in_sizes; (void)n_in; (void)out_size;
    const float* x        = (const float*)d_in[0];   // 8192 x 1024
    const float* patterns = (const float*)d_in[1];   // 4096 x 1024
    const float* Wq       = (const float*)d_in[2];   // 1024 x 1024
    const float* Wk       = (const float*)d_in[3];   // 1024 x 1024
    float* out = (float*)d_out;                      // 8192 x 1024

    float *sim;
    __half *stateh, *kh, *attnh, *patTh, *xh, *path, *wqh, *wkh;
    cudaGetSymbolAddress((void**)&stateh, g_stateh);
    cudaGetSymbolAddress((void**)&kh,     g_kh);
    cudaGetSymbolAddress((void**)&sim,    g_sim);
    cudaGetSymbolAddress((void**)&attnh,  g_attnh);
    cudaGetSymbolAddress((void**)&patTh,  g_patTh);
    cudaGetSymbolAddress((void**)&xh,     g_xh);
    cudaGetSymbolAddress((void**)&path,   g_path);
    cudaGetSymbolAddress((void**)&wqh,    g_wqh);
    cudaGetSymbolAddress((void**)&wkh,    g_wkh);

    cudaFuncSetAttribute(hgemm<0>, cudaFuncAttributeMaxDynamicSharedMemorySize, GEMM_SMEM_H);
    cudaFuncSetAttribute(hgemm<3>, cudaFuncAttributeMaxDynamicSharedMemorySize, GEMM_SMEM_H);
    cudaFuncSetAttribute(hgemm<4>, cudaFuncAttributeMaxDynamicSharedMemorySize, GEMM_SMEM_H);

    dim3 blk(128);

    // one-time fp16 conversions
    f2h_kernel<<<(ROWS_Q * DIM_C) / 1024, 256>>>(x, xh, ROWS_Q * DIM_C);
    f2h_kernel<<<(DIM_M * DIM_C) / 1024, 256>>>(patterns, path, DIM_M * DIM_C);
    f2h_kernel<<<(DIM_C * DIM_C) / 1024, 256>>>(Wq, wqh, DIM_C * DIM_C);
    f2h_kernel<<<(DIM_C * DIM_C) / 1024, 256>>>(Wk, wkh, DIM_C * DIM_C);
    transpose_h_kernel<<<dim3(DIM_M / 32, DIM_C / 32), dim3(256)>>>(patterns, patTh);

    // q = x @ Wq^T -> stateh (fp16)
    hgemm<3><<<dim3(DIM_C / 128, ROWS_Q / 128), blk, GEMM_SMEM_H>>>(
        xh, wqh, nullptr, stateh, nullptr, DIM_C, DIM_C);

    // k = patterns @ Wk^T -> kh (fp16)
    hgemm<3><<<dim3(DIM_C / 128, DIM_M / 128), blk, GEMM_SMEM_H>>>(
        path, wkh, nullptr, kh, nullptr, DIM_C, DIM_C);

    for (int it = 0; it < 4; it++) {
        // sim = state @ k^T (fp32 logits)
        hgemm<0><<<dim3(DIM_M / 128, ROWS_Q / 128), blk, GEMM_SMEM_H>>>(
            stateh, kh, sim, nullptr, nullptr, DIM_C, DIM_M);

        softmax_h_kernel<<<ROWS_Q, dim3(256)>>>(sim, attnh);

        if (it < 3) {
            // state = 0.5*state + 0.5*(attn @ patterns)  (fp16 in/out)
            hgemm<4><<<dim3(DIM_C / 128, ROWS_Q / 128), blk, GEMM_SMEM_H>>>(
                attnh, patTh, nullptr, stateh, stateh, DIM_M, DIM_C);
        } else {
            hgemm<0><<<dim3(DIM_C / 128, ROWS_Q / 128), blk, GEMM_SMEM_H>>>(
                attnh, patTh, out, nullptr, nullptr, DIM_M, DIM_C);
        }
    }
}